// round 15
// baseline (speedup 1.0000x reference)
#include <cuda_runtime.h>
#include <cstdint>

// YOLO loss v8: cp.async.bulk ring + dynamic tile stealing.
// pred [8192,49*30] f32, target [8192,49*25] f32 -> scalar f32.
// 296 blocks x 256 threads; 1568 tiles of 256 cells handed out by a
// global ticket counter (removes the R14 6/5 static-split tail).
// 2-stage smem ring (56.3KB/tile, 112.6KB -> 2 blocks/SM).
// Determinism: partials are PER-TILE (fixed reduction order inside a
// tile), summed in fixed tile order by the last block.

#define YS2        49
#define NT         256
#define TILE_C     256                 // cells per tile (= threads)
#define PF         (TILE_C * 30)       // 7680 floats pred / tile
#define TF         (TILE_C * 25)       // 6400 floats tgt  / tile
#define STF        (PF + TF)           // 14080 floats / stage
#define TILE_B     (STF * 4)           // 56320 bytes / stage
#define STAGES     2
#define SMEM_BYTES (STAGES * TILE_B)   // 112640 B
#define NTILES     1568                // 401408 / 256
#define NBLOCKS    296                 // 2 per SM
#define NBATCH     8192.0

__device__ double       g_partials[NTILES];
__device__ unsigned int g_next;        // tile ticket counter (reset by last block)
__device__ unsigned int g_ticket;      // completion counter   (reset by last block)

extern __shared__ __align__(16) float dsm[];

__device__ __forceinline__ void mbar_init(uint32_t a) {
    asm volatile("mbarrier.init.shared.b64 [%0], 1;" :: "r"(a) : "memory");
}
__device__ __forceinline__ void mbar_expect(uint32_t a, uint32_t bytes) {
    asm volatile("mbarrier.arrive.expect_tx.shared.b64 _, [%0], %1;"
                 :: "r"(a), "r"(bytes) : "memory");
}
__device__ __forceinline__ void bulk_cp(uint32_t dst, const void* src,
                                        uint32_t bytes, uint32_t mbar) {
    asm volatile(
        "cp.async.bulk.shared::cta.global.mbarrier::complete_tx::bytes "
        "[%0], [%1], %2, [%3];"
        :: "r"(dst), "l"(src), "r"(bytes), "r"(mbar) : "memory");
}
__device__ __forceinline__ void mbar_wait(uint32_t a, uint32_t parity) {
    asm volatile(
        "{\n\t.reg .pred P;\n\t"
        "WL_%=:\n\t"
        "mbarrier.try_wait.parity.acquire.cta.shared::cta.b64 P, [%0], %1, 0x989680;\n\t"
        "@P bra WD_%=;\n\t"
        "bra WL_%=;\n\t"
        "WD_%=:\n\t}"
        :: "r"(a), "r"(parity) : "memory");
}

__global__ __launch_bounds__(NT) void yolo_loss_kernel(
    const float* __restrict__ pred, const float* __restrict__ tgt,
    float* __restrict__ out)
{
    __shared__ __align__(8) unsigned long long mbar[STAGES];
    __shared__ int   s_tile[STAGES];   // ticket currently owning each slot
    __shared__ float wsum[NT / 32];
    __shared__ int   s_last;

    const int tid  = threadIdx.x;
    const int lane = tid & 31;
    const int wrp  = tid >> 5;

    const uint32_t mb0 = (uint32_t)__cvta_generic_to_shared(mbar);
    const uint32_t smb = (uint32_t)__cvta_generic_to_shared(dsm);

    if (tid == 0) {
        mbar_init(mb0);
        mbar_init(mb0 + 8);
        // prologue: grab and issue one tile per slot
        #pragma unroll
        for (int s = 0; s < STAGES; s++) {
            const int t = (int)atomicAdd(&g_next, 1u);
            s_tile[s] = t;
            if (t < NTILES) {
                const uint32_t mb  = mb0 + s * 8;
                const uint32_t dst = smb + (uint32_t)s * TILE_B;
                mbar_expect(mb, TILE_B);
                bulk_cp(dst,           pred + (size_t)t * PF, PF * 4, mb);
                bulk_cp(dst + PF * 4u, tgt  + (size_t)t * TF, TF * 4, mb);
            }
        }
    }
    __syncthreads();

    uint32_t phases = 0;

    for (int i = 0; ; i++) {
        const int slot = i & 1;
        const int t    = s_tile[slot];
        if (t >= NTILES) break;

        mbar_wait(mb0 + slot * 8, (phases >> slot) & 1u);
        phases ^= 1u << slot;

        const float* sp = dsm + slot * STF;     // pred tile
        const float* st = sp + PF;              // tgt tile
        const float* pc = sp + tid * 30;
        const float* tc = st + tid * 25;

        const int cell = t * TILE_C + tid;
        const float t0 = tc[0];
        const float p0 = pc[0];
        const float p5 = pc[5];

        float acc = 0.0f;
        if (t0 == 0.0f) {
            acc = 0.5f * (p0 * p0 + p5 * p5);
        } else if (t0 == 1.0f) {
            const int g    = cell % YS2;
            const float gy = (float)(g / 7);
            const float gx = (float)(g % 7);

            const float tx = tc[1], ty = tc[2], tw = tc[3], th = tc[4];
            const float tcx = (gx + tx) / 7.0f;
            const float tcy = (gy + ty) / 7.0f;
            const float tx1 = tcx - tw * 0.5f, ty1 = tcy - th * 0.5f;
            const float tx2 = tcx + tw * 0.5f, ty2 = tcy + th * 0.5f;
            const float area_t = (tx2 - tx1) * (ty2 - ty1);

            float bx[2][4];
            #pragma unroll
            for (int bb = 0; bb < 2; bb++)
                #pragma unroll
                for (int j = 0; j < 4; j++)
                    bx[bb][j] = pc[bb * 5 + 1 + j];

            float iou[2];
            #pragma unroll
            for (int bb = 0; bb < 2; bb++) {
                const float px = fabsf(bx[bb][0]);
                const float py = fabsf(bx[bb][1]);
                const float pw = fabsf(bx[bb][2]);
                const float ph = fabsf(bx[bb][3]);
                const float cx = (gx + px) / 7.0f;
                const float cy = (gy + py) / 7.0f;
                const float x1 = cx - pw * 0.5f, y1 = cy - ph * 0.5f;
                const float x2 = cx + pw * 0.5f, y2 = cy + ph * 0.5f;
                const float ltx = fmaxf(x1, tx1), lty = fmaxf(y1, ty1);
                const float rbx = fminf(x2, tx2), rby = fminf(y2, ty2);
                const float iw  = fmaxf(rbx - ltx, 0.0f);
                const float ih  = fmaxf(rby - lty, 0.0f);
                const float inter  = iw * ih;
                const float area_p = (x2 - x1) * (y2 - y1);
                iou[bb] = inter / (area_p + area_t - inter);
            }

            const int   best    = (iou[1] > iou[0]) ? 1 : 0;  // tie -> box 0
            const float max_iou = best ? iou[1] : iou[0];
            const float rconf   = best ? p5 : p0;

            const float dx = bx[best][0] - tx;
            const float dy = bx[best][1] - ty;
            const float xy_loss = dx * dx + dy * dy;

            const float swd = sqrtf(fabsf(bx[best][2])) - sqrtf(fabsf(tw));
            const float shd = sqrtf(fabsf(bx[best][3])) - sqrtf(fabsf(th));
            const float wh_loss = swd * swd + shd * shd;

            const float doc = rconf - max_iou;
            const float obj_conf = doc * doc;

            float cls = 0.0f;
            #pragma unroll
            for (int j = 0; j < 20; j++) {
                const float d = pc[10 + j] - tc[5 + j];
                cls += d * d;
            }

            acc = 5.0f * (xy_loss + wh_loss) + obj_conf + cls;
        }

        // ---- per-tile deterministic reduction ----
        #pragma unroll
        for (int o = 16; o > 0; o >>= 1)
            acc += __shfl_down_sync(0xffffffffu, acc, o);
        if (lane == 0) wsum[wrp] = acc;
        __syncthreads();     // compute + reduce done; slot safe to refill

        if (tid == 0) {
            double s = 0.0;
            #pragma unroll
            for (int w = 0; w < NT / 32; w++) s += (double)wsum[w];
            g_partials[t] = s;

            // steal next tile into this slot
            const int tn = (int)atomicAdd(&g_next, 1u);
            s_tile[slot] = tn;
            if (tn < NTILES) {
                const uint32_t mb  = mb0 + slot * 8;
                const uint32_t dst = smb + (uint32_t)slot * TILE_B;
                mbar_expect(mb, TILE_B);
                bulk_cp(dst,           pred + (size_t)tn * PF, PF * 4, mb);
                bulk_cp(dst + PF * 4u, tgt  + (size_t)tn * TF, TF * 4, mb);
            }
        }
        __syncthreads();     // s_tile[slot] visible to all threads
    }

    // ---- completion ticket ----
    if (tid == 0) {
        __threadfence();
        unsigned int ticket = atomicAdd(&g_ticket, 1u);
        s_last = (ticket == NBLOCKS - 1u) ? 1 : 0;
    }
    __syncthreads();

    // ---- last block: final reduction over per-tile partials ----
    if (s_last) {
        __threadfence();
        __shared__ double dsum[NT / 32];

        double s = 0.0;
        for (int i = tid; i < NTILES; i += NT)
            s += g_partials[i];

        #pragma unroll
        for (int o = 16; o > 0; o >>= 1)
            s += __shfl_down_sync(0xffffffffu, s, o);

        if (lane == 0) dsum[wrp] = s;
        __syncthreads();

        if (tid == 0) {
            double total = 0.0;
            #pragma unroll
            for (int w = 0; w < NT / 32; w++) total += dsum[w];
            out[0] = (float)(total / NBATCH);
            g_ticket = 0;    // reset for next graph replay
            g_next   = 0;
        }
    }
}

extern "C" void kernel_launch(void* const* d_in, const int* in_sizes, int n_in,
                              void* d_out, int out_size)
{
    const float* pred = (const float*)d_in[0];
    const float* tgt  = (const float*)d_in[1];
    float* out        = (float*)d_out;

    cudaFuncSetAttribute(yolo_loss_kernel,
                         cudaFuncAttributeMaxDynamicSharedMemorySize,
                         SMEM_BYTES);
    yolo_loss_kernel<<<NBLOCKS, NT, SMEM_BYTES>>>(pred, tgt, out);
}

// round 16
// speedup vs baseline: 1.3043x; 1.3043x over previous
#include <cuda_runtime.h>
#include <cstdint>

// YOLO loss v9: R14 bulk-copy ring + SM-aware static tile split.
// pred [8192,49*30] f32, target [8192,49*25] f32 -> scalar f32.
// 296 blocks x 256 threads; 1568 tiles of 256 cells; 2-stage smem ring
// (56.3KB/stage, 112.6KB -> 2 blocks/SM = 16 warps/SM).
// Placement fact: block b and b+148 share an SM (LUT[bid%148]) -> assign
// per-SM totals (88 SMs x 11, 60 SMs x 10), split 6+5 / 5+5 within the SM.
// Max per-SM skew drops from 2 tiles (R14) to 1.
// Fused deterministic reduction (ticket + last block).

#define YS2        49
#define NT         256
#define TILE_C     256                 // cells per tile (= threads)
#define PF         (TILE_C * 30)       // 7680 floats pred / tile
#define TF         (TILE_C * 25)       // 6400 floats tgt  / tile
#define STF        (PF + TF)           // 14080 floats / stage
#define TILE_B     (STF * 4)           // 56320 bytes / stage
#define STAGES     2
#define SMEM_BYTES (STAGES * TILE_B)   // 112640 B
#define NTILES     1568                // 401408 / 256
#define NBLOCKS    296                 // 2 per SM
#define NBATCH     8192.0

__device__ double       g_partials[NBLOCKS];
__device__ unsigned int g_ticket;      // zero-init; reset by last block

extern __shared__ __align__(16) float dsm[];

__device__ __forceinline__ void mbar_init(uint32_t a) {
    asm volatile("mbarrier.init.shared.b64 [%0], 1;" :: "r"(a) : "memory");
}
__device__ __forceinline__ void mbar_expect(uint32_t a, uint32_t bytes) {
    asm volatile("mbarrier.arrive.expect_tx.shared.b64 _, [%0], %1;"
                 :: "r"(a), "r"(bytes) : "memory");
}
__device__ __forceinline__ void bulk_cp(uint32_t dst, const void* src,
                                        uint32_t bytes, uint32_t mbar) {
    asm volatile(
        "cp.async.bulk.shared::cta.global.mbarrier::complete_tx::bytes "
        "[%0], [%1], %2, [%3];"
        :: "r"(dst), "l"(src), "r"(bytes), "r"(mbar) : "memory");
}
__device__ __forceinline__ void mbar_wait(uint32_t a, uint32_t parity) {
    asm volatile(
        "{\n\t.reg .pred P;\n\t"
        "WL_%=:\n\t"
        "mbarrier.try_wait.parity.acquire.cta.shared::cta.b64 P, [%0], %1, 0x989680;\n\t"
        "@P bra WD_%=;\n\t"
        "bra WL_%=;\n\t"
        "WD_%=:\n\t}"
        :: "r"(a), "r"(parity) : "memory");
}

__global__ __launch_bounds__(NT) void yolo_loss_kernel(
    const float* __restrict__ pred, const float* __restrict__ tgt,
    float* __restrict__ out)
{
    __shared__ __align__(8) unsigned long long mbar[STAGES];
    __shared__ float wsum[NT / 32];
    __shared__ int   s_last;

    const int tid = threadIdx.x;
    const int b   = blockIdx.x;

    // ---- SM-aware static split ----
    // sm = b % 148 (block b and b+148 co-reside). SMs 0..87 own 11 tiles
    // (split 6+5), SMs 88..147 own 10 (split 5+5).
    const int sm   = b % 148;
    const int wave = b / 148;
    const int smstart = (sm < 88) ? (11 * sm) : (10 * sm + 88);
    const int cnt0    = (sm < 88) ? 6 : 5;
    const int start   = (wave == 0) ? smstart : (smstart + cnt0);
    const int cnt     = (wave == 0) ? cnt0 : 5;

    const uint32_t mb0 = (uint32_t)__cvta_generic_to_shared(mbar);
    const uint32_t smb = (uint32_t)__cvta_generic_to_shared(dsm);

    if (tid == 0) {
        mbar_init(mb0);
        mbar_init(mb0 + 8);
    }
    __syncthreads();

    auto issue = [&](int i) {
        const int slot = i & 1;
        const int t    = start + i;
        const uint32_t mb  = mb0 + slot * 8;
        const uint32_t dst = smb + (uint32_t)slot * TILE_B;
        mbar_expect(mb, TILE_B);
        bulk_cp(dst,           pred + (size_t)t * PF, PF * 4, mb);
        bulk_cp(dst + PF * 4u, tgt  + (size_t)t * TF, TF * 4, mb);
    };

    if (tid == 0) issue(0);

    float acc = 0.0f;

    for (int i = 0; i < cnt; i++) {
        if (tid == 0 && i + 1 < cnt) issue(i + 1);

        const int slot = i & 1;
        mbar_wait(mb0 + slot * 8, (i >> 1) & 1);

        const float* sp = dsm + slot * STF;     // pred tile
        const float* st = sp + PF;              // tgt tile
        const float* pc = sp + tid * 30;
        const float* tc = st + tid * 25;

        const int cell = (start + i) * TILE_C + tid;
        const float t0 = tc[0];
        const float p0 = pc[0];
        const float p5 = pc[5];

        if (t0 == 0.0f) {
            acc += 0.5f * (p0 * p0 + p5 * p5);
        } else if (t0 == 1.0f) {
            const int g    = cell % YS2;
            const float gy = (float)(g / 7);
            const float gx = (float)(g % 7);

            const float tx = tc[1], ty = tc[2], tw = tc[3], th = tc[4];
            const float tcx = (gx + tx) / 7.0f;
            const float tcy = (gy + ty) / 7.0f;
            const float tx1 = tcx - tw * 0.5f, ty1 = tcy - th * 0.5f;
            const float tx2 = tcx + tw * 0.5f, ty2 = tcy + th * 0.5f;
            const float area_t = (tx2 - tx1) * (ty2 - ty1);

            float bx[2][4];
            #pragma unroll
            for (int bb = 0; bb < 2; bb++)
                #pragma unroll
                for (int j = 0; j < 4; j++)
                    bx[bb][j] = pc[bb * 5 + 1 + j];

            float iou[2];
            #pragma unroll
            for (int bb = 0; bb < 2; bb++) {
                const float px = fabsf(bx[bb][0]);
                const float py = fabsf(bx[bb][1]);
                const float pw = fabsf(bx[bb][2]);
                const float ph = fabsf(bx[bb][3]);
                const float cx = (gx + px) / 7.0f;
                const float cy = (gy + py) / 7.0f;
                const float x1 = cx - pw * 0.5f, y1 = cy - ph * 0.5f;
                const float x2 = cx + pw * 0.5f, y2 = cy + ph * 0.5f;
                const float ltx = fmaxf(x1, tx1), lty = fmaxf(y1, ty1);
                const float rbx = fminf(x2, tx2), rby = fminf(y2, ty2);
                const float iw  = fmaxf(rbx - ltx, 0.0f);
                const float ih  = fmaxf(rby - lty, 0.0f);
                const float inter  = iw * ih;
                const float area_p = (x2 - x1) * (y2 - y1);
                iou[bb] = inter / (area_p + area_t - inter);
            }

            const int   best    = (iou[1] > iou[0]) ? 1 : 0;  // tie -> box 0
            const float max_iou = best ? iou[1] : iou[0];
            const float rconf   = best ? p5 : p0;

            const float dx = bx[best][0] - tx;
            const float dy = bx[best][1] - ty;
            const float xy_loss = dx * dx + dy * dy;

            const float swd = sqrtf(fabsf(bx[best][2])) - sqrtf(fabsf(tw));
            const float shd = sqrtf(fabsf(bx[best][3])) - sqrtf(fabsf(th));
            const float wh_loss = swd * swd + shd * shd;

            const float doc = rconf - max_iou;
            const float obj_conf = doc * doc;

            float cls = 0.0f;
            #pragma unroll
            for (int j = 0; j < 20; j++) {
                const float d = pc[10 + j] - tc[5 + j];
                cls += d * d;
            }

            acc += 5.0f * (xy_loss + wh_loss) + obj_conf + cls;
        }

        __syncthreads();        // all threads done with this slot
    }

    // ---- deterministic block reduction ----
    #pragma unroll
    for (int o = 16; o > 0; o >>= 1)
        acc += __shfl_down_sync(0xffffffffu, acc, o);

    const int lane = tid & 31;
    const int wrp  = tid >> 5;
    if (lane == 0) wsum[wrp] = acc;
    __syncthreads();

    if (tid == 0) {
        double s = 0.0;
        #pragma unroll
        for (int w = 0; w < NT / 32; w++) s += (double)wsum[w];
        g_partials[b] = s;
        __threadfence();
        unsigned int ticket = atomicAdd(&g_ticket, 1u);
        s_last = (ticket == NBLOCKS - 1u) ? 1 : 0;
    }
    __syncthreads();

    // ---- last block: final reduction over all partials ----
    if (s_last) {
        __threadfence();
        __shared__ double dsum[NT / 32];

        double s = 0.0;
        for (int i = tid; i < NBLOCKS; i += NT)
            s += g_partials[i];

        #pragma unroll
        for (int o = 16; o > 0; o >>= 1)
            s += __shfl_down_sync(0xffffffffu, s, o);

        if (lane == 0) dsum[wrp] = s;
        __syncthreads();

        if (tid == 0) {
            double total = 0.0;
            #pragma unroll
            for (int w = 0; w < NT / 32; w++) total += dsum[w];
            out[0] = (float)(total / NBATCH);
            g_ticket = 0;   // reset for next graph replay
        }
    }
}

extern "C" void kernel_launch(void* const* d_in, const int* in_sizes, int n_in,
                              void* d_out, int out_size)
{
    const float* pred = (const float*)d_in[0];
    const float* tgt  = (const float*)d_in[1];
    float* out        = (float*)d_out;

    cudaFuncSetAttribute(yolo_loss_kernel,
                         cudaFuncAttributeMaxDynamicSharedMemorySize,
                         SMEM_BYTES);
    yolo_loss_kernel<<<NBLOCKS, NT, SMEM_BYTES>>>(pred, tgt, out);
}